// round 7
// baseline (speedup 1.0000x reference)
#include <cuda_runtime.h>
#include <cuda_bf16.h>
#include <cstdint>

// ---------------------------------------------------------------------------
// CompositionModel fused kernel (tf32 mma.sync path)
//   Xp = [log1p(X) | Z[c2b]]  (N x 160)
//   h1 = relu(Xp@W1+b1)  (N x 256)
//   h2 = relu(h1@W2+b2)  (N x 256)
//   Xc = h2@W3+b3        (N x 16)
//   Y  = segment_mean(Xc, seg)  (512 x 16)
// NOTE: cell_to_batch / sample_idx_batch are INT32 on the wire (JAX x64 off).
// ---------------------------------------------------------------------------

#define N_CELLS 500000
#define D_X     128
#define D_Z     32
#define D_IN    160
#define HID     256
#define D_OUT   16
#define BATCH   512
#define TILE_M  128
#define LDA     260          // smem row stride (floats); 260%32==4 -> conflict-free frags
#define NTILES  ((N_CELLS + TILE_M - 1) / TILE_M)   // 3907

// smem layout (floats): sBuf[128*260] | sSeg[128](int) | sCB[128](int) | sB1[256] sB2[256] sB3[16]
#define SMEM_BYTES ((128 * LDA) * 4 + 128 * 4 * 2 + (256 + 256 + 16) * 4)

// __device__ scratch (allowed; no runtime allocation)
__device__ float gW1[D_IN * HID];     // tf32-rounded weights
__device__ float gW2[HID * HID];
__device__ float gW3[HID * D_OUT];
__device__ float gSum[BATCH * D_OUT];
__device__ float gCnt[BATCH];

__device__ __forceinline__ float tf32r(float x) {
    uint32_t u;
    asm("cvt.rna.tf32.f32 %0, %1;" : "=r"(u) : "f"(x));
    return __uint_as_float(u);
}

__device__ __forceinline__ void mma8(float c[4],
                                     uint32_t a0, uint32_t a1, uint32_t a2, uint32_t a3,
                                     uint32_t b0, uint32_t b1) {
    asm volatile(
        "mma.sync.aligned.m16n8k8.row.col.f32.tf32.tf32.f32 "
        "{%0,%1,%2,%3}, {%4,%5,%6,%7}, {%8,%9}, {%0,%1,%2,%3};\n"
        : "+f"(c[0]), "+f"(c[1]), "+f"(c[2]), "+f"(c[3])
        : "r"(a0), "r"(a1), "r"(a2), "r"(a3), "r"(b0), "r"(b1));
}

// 64(M) x 64(N) warp tile GEMM: C += A(sBuf rows m0..m0+63, cols 0..K-1) @ W(K x ldw)
template <int KTOT>
__device__ __forceinline__ void gemm64x64(const float* __restrict__ sBuf,
                                          const float* __restrict__ W, int ldw,
                                          int m0, int n0, int g, int tig,
                                          float (&acc)[4][8][4]) {
    for (int k0 = 0; k0 < KTOT; k0 += 8) {
        uint32_t a[4][4];
#pragma unroll
        for (int mt = 0; mt < 4; mt++) {
            const float* p  = sBuf + (m0 + mt * 16 + g) * LDA + k0 + tig;
            const float* p8 = p + 8 * LDA;
            a[mt][0] = __float_as_uint(p[0]);
            a[mt][1] = __float_as_uint(p8[0]);
            a[mt][2] = __float_as_uint(p[4]);
            a[mt][3] = __float_as_uint(p8[4]);
        }
#pragma unroll
        for (int nt = 0; nt < 8; nt++) {
            int col = n0 + nt * 8 + g;
            uint32_t b0 = __float_as_uint(W[(k0 + tig) * ldw + col]);
            uint32_t b1 = __float_as_uint(W[(k0 + tig + 4) * ldw + col]);
#pragma unroll
            for (int mt = 0; mt < 4; mt++)
                mma8(acc[mt][nt], a[mt][0], a[mt][1], a[mt][2], a[mt][3], b0, b1);
        }
    }
}

__device__ __forceinline__ void store_act(float* sBuf, const float* bias,
                                          int m0, int n0, int g, int tig,
                                          float (&acc)[4][8][4]) {
#pragma unroll
    for (int mt = 0; mt < 4; mt++) {
        int r0 = m0 + mt * 16 + g;
#pragma unroll
        for (int nt = 0; nt < 8; nt++) {
            int c0 = n0 + nt * 8 + 2 * tig;
            float bv0 = bias[c0], bv1 = bias[c0 + 1];
            float2 v;
            v.x = tf32r(fmaxf(acc[mt][nt][0] + bv0, 0.0f));
            v.y = tf32r(fmaxf(acc[mt][nt][1] + bv1, 0.0f));
            *reinterpret_cast<float2*>(sBuf + r0 * LDA + c0) = v;
            v.x = tf32r(fmaxf(acc[mt][nt][2] + bv0, 0.0f));
            v.y = tf32r(fmaxf(acc[mt][nt][3] + bv1, 0.0f));
            *reinterpret_cast<float2*>(sBuf + (r0 + 8) * LDA + c0) = v;
        }
    }
}

// ---------------------------------------------------------------------------
// prep: tf32-round weights into __device__ scratch, zero accumulators
// ---------------------------------------------------------------------------
__global__ void prep_kernel(const float* __restrict__ W1,
                            const float* __restrict__ W2,
                            const float* __restrict__ W3) {
    int stride = gridDim.x * blockDim.x;
    int t0 = blockIdx.x * blockDim.x + threadIdx.x;
    for (int i = t0; i < D_IN * HID; i += stride)  gW1[i] = tf32r(W1[i]);
    for (int i = t0; i < HID * HID; i += stride)   gW2[i] = tf32r(W2[i]);
    for (int i = t0; i < HID * D_OUT; i += stride) gW3[i] = tf32r(W3[i]);
    for (int i = t0; i < BATCH * D_OUT; i += stride) gSum[i] = 0.0f;
    for (int i = t0; i < BATCH; i += stride)         gCnt[i] = 0.0f;
}

// ---------------------------------------------------------------------------
// fused main kernel: one CTA = 128 cells, 8 warps
//   warps tiled 2(M-groups of 64 rows) x 4(N-groups of 64 cols) for layers 1/2
//   layer 3: each warp owns 16 rows, N=16
// ---------------------------------------------------------------------------
__global__ __launch_bounds__(256) void fused_kernel(
    const float* __restrict__ X, const float* __restrict__ Z,
    const float* __restrict__ b1, const float* __restrict__ b2,
    const float* __restrict__ b3,
    const int* __restrict__ c2b, const int* __restrict__ sidx) {
    extern __shared__ float smem[];
    float* sBuf = smem;                               // 128 x LDA
    int*   sSeg = (int*)(smem + 128 * LDA);           // 128
    int*   sCB  = sSeg + 128;                         // 128
    float* sB1  = (float*)(sCB + 128);                // 256
    float* sB2  = sB1 + 256;                          // 256
    float* sB3  = sB2 + 256;                          // 16

    const int tid  = threadIdx.x;
    const int lane = tid & 31;
    const int wid  = tid >> 5;
    const int g    = lane >> 2;
    const int tig  = lane & 3;
    const int base = blockIdx.x * TILE_M;

    // ---- phase A: indices + biases ----
    if (tid < 128) {
        int c = base + tid, cb = 0, seg = -1;
        if (c < N_CELLS) { cb = c2b[c]; seg = sidx[cb]; }
        sCB[tid] = cb;
        sSeg[tid] = seg;
    }
    if (tid < 256) { sB1[tid] = b1[tid]; sB2[tid] = b2[tid]; }
    if (tid < 16) sB3[tid] = b3[tid];
    __syncthreads();

    // ---- phase B: build Xp tile (tf32-rounded) ----
    for (int idx = tid; idx < 128 * 32; idx += 256) {      // X part: log1p
        int row = idx >> 5, q = idx & 31;
        int c = base + row;
        float4 v = make_float4(0.f, 0.f, 0.f, 0.f);
        if (c < N_CELLS) {
            float4 x = *reinterpret_cast<const float4*>(X + (size_t)c * D_X + q * 4);
            v.x = tf32r(__logf(1.0f + x.x));
            v.y = tf32r(__logf(1.0f + x.y));
            v.z = tf32r(__logf(1.0f + x.z));
            v.w = tf32r(__logf(1.0f + x.w));
        }
        *reinterpret_cast<float4*>(sBuf + row * LDA + q * 4) = v;
    }
    for (int idx = tid; idx < 128 * 8; idx += 256) {       // Z part: gather
        int row = idx >> 3, q = idx & 7;
        int c = base + row;
        float4 v = make_float4(0.f, 0.f, 0.f, 0.f);
        if (c < N_CELLS) {
            float4 z = *reinterpret_cast<const float4*>(Z + (size_t)sCB[row] * D_Z + q * 4);
            v.x = tf32r(z.x); v.y = tf32r(z.y); v.z = tf32r(z.z); v.w = tf32r(z.w);
        }
        *reinterpret_cast<float4*>(sBuf + row * LDA + D_X + q * 4) = v;
    }
    __syncthreads();

    const int mg = wid & 1, ng = wid >> 1;
    const int m0 = mg * 64, n0 = ng * 64;

    float acc[4][8][4];

    // ---- layer 1: Xp(128x160) @ W1(160x256) ----
#pragma unroll
    for (int mt = 0; mt < 4; mt++)
#pragma unroll
        for (int nt = 0; nt < 8; nt++)
#pragma unroll
            for (int i = 0; i < 4; i++) acc[mt][nt][i] = 0.0f;
    gemm64x64<D_IN>(sBuf, gW1, HID, m0, n0, g, tig, acc);
    __syncthreads();                       // all reads of Xp done before overwrite
    store_act(sBuf, sB1, m0, n0, g, tig, acc);
    __syncthreads();

    // ---- layer 2: h1(128x256) @ W2(256x256) ----
#pragma unroll
    for (int mt = 0; mt < 4; mt++)
#pragma unroll
        for (int nt = 0; nt < 8; nt++)
#pragma unroll
            for (int i = 0; i < 4; i++) acc[mt][nt][i] = 0.0f;
    gemm64x64<HID>(sBuf, gW2, HID, m0, n0, g, tig, acc);
    __syncthreads();
    store_act(sBuf, sB2, m0, n0, g, tig, acc);
    __syncthreads();

    // ---- layer 3: h2(128x256) @ W3(256x16); each warp owns 16 rows ----
    float acc3[2][4];
#pragma unroll
    for (int nt = 0; nt < 2; nt++)
#pragma unroll
        for (int i = 0; i < 4; i++) acc3[nt][i] = 0.0f;

    const int r0w = wid * 16;
    for (int k0 = 0; k0 < HID; k0 += 8) {
        const float* p  = sBuf + (r0w + g) * LDA + k0 + tig;
        const float* p8 = p + 8 * LDA;
        uint32_t a0 = __float_as_uint(p[0]);
        uint32_t a1 = __float_as_uint(p8[0]);
        uint32_t a2 = __float_as_uint(p[4]);
        uint32_t a3 = __float_as_uint(p8[4]);
#pragma unroll
        for (int nt = 0; nt < 2; nt++) {
            int col = nt * 8 + g;
            uint32_t b0 = __float_as_uint(gW3[(k0 + tig) * D_OUT + col]);
            uint32_t b1 = __float_as_uint(gW3[(k0 + tig + 4) * D_OUT + col]);
            mma8(acc3[nt], a0, a1, a2, a3, b0, b1);
        }
    }

    // ---- epilogue: bias + segment reduction (RED atomics) ----
    const int rA = r0w + g, rB = rA + 8;
    const int segA = sSeg[rA], segB = sSeg[rB];
#pragma unroll
    for (int nt = 0; nt < 2; nt++) {
        int c0 = nt * 8 + 2 * tig;
        float bv0 = sB3[c0], bv1 = sB3[c0 + 1];
        if (segA >= 0) {
            atomicAdd(&gSum[segA * D_OUT + c0],     acc3[nt][0] + bv0);
            atomicAdd(&gSum[segA * D_OUT + c0 + 1], acc3[nt][1] + bv1);
        }
        if (segB >= 0) {
            atomicAdd(&gSum[segB * D_OUT + c0],     acc3[nt][2] + bv0);
            atomicAdd(&gSum[segB * D_OUT + c0 + 1], acc3[nt][3] + bv1);
        }
    }
    if (tig == 0) {
        if (segA >= 0) atomicAdd(&gCnt[segA], 1.0f);
        if (segB >= 0) atomicAdd(&gCnt[segB], 1.0f);
    }
}

// ---------------------------------------------------------------------------
__global__ void finalize_kernel(float* __restrict__ out) {
    int i = blockIdx.x * blockDim.x + threadIdx.x;
    if (i < BATCH * D_OUT)
        out[i] = gSum[i] / fmaxf(gCnt[i >> 4], 1.0f);
}

// ---------------------------------------------------------------------------
extern "C" void kernel_launch(void* const* d_in, const int* in_sizes, int n_in,
                              void* d_out, int out_size) {
    const float* X    = (const float*)d_in[0];
    const float* Z    = (const float*)d_in[1];
    const float* W1   = (const float*)d_in[2];
    const float* b1   = (const float*)d_in[3];
    const float* W2   = (const float*)d_in[4];
    const float* b2   = (const float*)d_in[5];
    const float* W3   = (const float*)d_in[6];
    const float* b3   = (const float*)d_in[7];
    const int*   c2b  = (const int*)d_in[8];    // int32 on the wire (JAX x64 off)
    const int*   sidx = (const int*)d_in[9];    // int32 on the wire
    float* out = (float*)d_out;

    cudaFuncSetAttribute(fused_kernel, cudaFuncAttributeMaxDynamicSharedMemorySize,
                         SMEM_BYTES);

    prep_kernel<<<160, 256>>>(W1, W2, W3);
    fused_kernel<<<NTILES, 256, SMEM_BYTES>>>(X, Z, b1, b2, b3, c2b, sidx);
    finalize_kernel<<<(BATCH * D_OUT + 255) / 256, 256>>>(out);
}

// round 8
// speedup vs baseline: 2.2851x; 2.2851x over previous
#include <cuda_runtime.h>
#include <cuda_bf16.h>
#include <cstdint>

// ---------------------------------------------------------------------------
// CompositionModel fused kernel — tf32 mma.sync + cp.async weight staging
//   Xp = [log1p(X) | Z[c2b]]  (N x 160)
//   h1 = relu(Xp@W1+b1)  (N x 256)
//   h2 = relu(h1@W2+b2)  (N x 256)
//   Xc = h2@W3+b3        (N x 16)
//   Y  = segment_mean(Xc, seg)  (512 x 16)
// R7 change: weights streamed global->smem with 2-stage cp.async pipeline.
// Previously B-fragments were per-k-step LDGs hitting L2 (~240 cyc) because
// L1 carveout (92 KB) < weight set (420 KB)  -> latency-bound at 41 cyc/MMA.
// ---------------------------------------------------------------------------

#define N_CELLS 500000
#define D_X     128
#define D_Z     32
#define D_IN    160
#define HID     256
#define D_OUT   16
#define BATCH   512
#define TILE_M  128
#define LDA     260          // act row stride (floats): 260%32==4 -> conflict-free A frags
#define LDB     264          // weight-stage row stride: 264%32==8 -> bank 8*tig+g, injective
#define LDB3    24           // W3 stage row stride: offsets {0,24,16,8}+g distinct mod 32
#define KC      32           // k-chunk (rows per stage)
#define STAGE_FLOATS (KC * LDB)             // 8448
#define NTILES  ((N_CELLS + TILE_M - 1) / TILE_M)   // 3907

// smem (floats): sBuf[128*LDA] | stage0[8448] | stage1[8448] | sSeg[128] sCB[128] | sB1[256] sB2[256] sB3[16]
#define SMEM_FLOATS (128 * LDA + 2 * STAGE_FLOATS)
#define SMEM_BYTES  (SMEM_FLOATS * 4 + 128 * 4 * 2 + (256 + 256 + 16) * 4)

__device__ float gW1[D_IN * HID];     // tf32-rounded weights
__device__ float gW2[HID * HID];
__device__ float gW3[HID * D_OUT];
__device__ float gSum[BATCH * D_OUT];
__device__ float gCnt[BATCH];

__device__ __forceinline__ float tf32r(float x) {
    uint32_t u;
    asm("cvt.rna.tf32.f32 %0, %1;" : "=r"(u) : "f"(x));
    return __uint_as_float(u);
}

__device__ __forceinline__ void cp16(float* dst_smem, const float* src) {
    uint32_t d = (uint32_t)__cvta_generic_to_shared(dst_smem);
    asm volatile("cp.async.cg.shared.global [%0], [%1], 16;\n" :: "r"(d), "l"(src));
}
__device__ __forceinline__ void cp_commit() {
    asm volatile("cp.async.commit_group;\n");
}
template <int N>
__device__ __forceinline__ void cp_wait() {
    asm volatile("cp.async.wait_group %0;\n" :: "n"(N));
}

__device__ __forceinline__ void mma8(float c[4],
                                     uint32_t a0, uint32_t a1, uint32_t a2, uint32_t a3,
                                     uint32_t b0, uint32_t b1) {
    asm volatile(
        "mma.sync.aligned.m16n8k8.row.col.f32.tf32.tf32.f32 "
        "{%0,%1,%2,%3}, {%4,%5,%6,%7}, {%8,%9}, {%0,%1,%2,%3};\n"
        : "+f"(c[0]), "+f"(c[1]), "+f"(c[2]), "+f"(c[3])
        : "r"(a0), "r"(a1), "r"(a2), "r"(a3), "r"(b0), "r"(b1));
}

// prefetch one KC x 256 weight chunk into a stage buffer (2048 float4, 8/thread)
__device__ __forceinline__ void prefetch_chunk(float* sW, const float* Wg, int chunk) {
    const float* src = Wg + (size_t)chunk * KC * HID;
    int t = threadIdx.x;
#pragma unroll
    for (int j = 0; j < 8; j++) {
        int idx = t + j * 256;            // 0..2047
        int row = idx >> 6, cv = idx & 63;
        cp16(sW + row * LDB + cv * 4, src + row * HID + cv * 4);
    }
}

// prefetch W3 (256 x 16) into stage area with LDB3 stride (1024 float4, 4/thread)
__device__ __forceinline__ void prefetch_w3(float* sW3, const float* Wg) {
    int t = threadIdx.x;
#pragma unroll
    for (int j = 0; j < 4; j++) {
        int idx = t + j * 256;            // 0..1023
        int row = idx >> 2, cv = idx & 3;
        cp16(sW3 + row * LDB3 + cv * 4, Wg + row * D_OUT + cv * 4);
    }
}

// one KC-wide slab of the 64x64 warp-tile GEMM; A cols [kbase, kbase+KC), B from stage
__device__ __forceinline__ void compute_chunk(const float* __restrict__ sBuf,
                                              const float* __restrict__ sW,
                                              int m0, int n0, int g, int tig, int kbase,
                                              float (&acc)[4][8][4]) {
#pragma unroll
    for (int kk = 0; kk < KC; kk += 8) {
        uint32_t a[4][4];
#pragma unroll
        for (int mt = 0; mt < 4; mt++) {
            const float* p  = sBuf + (m0 + mt * 16 + g) * LDA + kbase + kk + tig;
            const float* p8 = p + 8 * LDA;
            a[mt][0] = __float_as_uint(p[0]);
            a[mt][1] = __float_as_uint(p8[0]);
            a[mt][2] = __float_as_uint(p[4]);
            a[mt][3] = __float_as_uint(p8[4]);
        }
#pragma unroll
        for (int nt = 0; nt < 8; nt++) {
            int col = n0 + nt * 8 + g;
            uint32_t b0 = __float_as_uint(sW[(kk + tig) * LDB + col]);
            uint32_t b1 = __float_as_uint(sW[(kk + tig + 4) * LDB + col]);
#pragma unroll
            for (int mt = 0; mt < 4; mt++)
                mma8(acc[mt][nt], a[mt][0], a[mt][1], a[mt][2], a[mt][3], b0, b1);
        }
    }
}

__device__ __forceinline__ void store_act(float* sBuf, const float* bias,
                                          int m0, int n0, int g, int tig,
                                          float (&acc)[4][8][4]) {
#pragma unroll
    for (int mt = 0; mt < 4; mt++) {
        int r0 = m0 + mt * 16 + g;
#pragma unroll
        for (int nt = 0; nt < 8; nt++) {
            int c0 = n0 + nt * 8 + 2 * tig;
            float bv0 = bias[c0], bv1 = bias[c0 + 1];
            float2 v;
            v.x = tf32r(fmaxf(acc[mt][nt][0] + bv0, 0.0f));
            v.y = tf32r(fmaxf(acc[mt][nt][1] + bv1, 0.0f));
            *reinterpret_cast<float2*>(sBuf + r0 * LDA + c0) = v;
            v.x = tf32r(fmaxf(acc[mt][nt][2] + bv0, 0.0f));
            v.y = tf32r(fmaxf(acc[mt][nt][3] + bv1, 0.0f));
            *reinterpret_cast<float2*>(sBuf + (r0 + 8) * LDA + c0) = v;
        }
    }
}

// ---------------------------------------------------------------------------
__global__ void prep_kernel(const float* __restrict__ W1,
                            const float* __restrict__ W2,
                            const float* __restrict__ W3) {
    int stride = gridDim.x * blockDim.x;
    int t0 = blockIdx.x * blockDim.x + threadIdx.x;
    for (int i = t0; i < D_IN * HID; i += stride)  gW1[i] = tf32r(W1[i]);
    for (int i = t0; i < HID * HID; i += stride)   gW2[i] = tf32r(W2[i]);
    for (int i = t0; i < HID * D_OUT; i += stride) gW3[i] = tf32r(W3[i]);
    for (int i = t0; i < BATCH * D_OUT; i += stride) gSum[i] = 0.0f;
    for (int i = t0; i < BATCH; i += stride)         gCnt[i] = 0.0f;
}

// ---------------------------------------------------------------------------
__global__ __launch_bounds__(256) void fused_kernel(
    const float* __restrict__ X, const float* __restrict__ Z,
    const float* __restrict__ b1, const float* __restrict__ b2,
    const float* __restrict__ b3,
    const int* __restrict__ c2b, const int* __restrict__ sidx) {
    extern __shared__ float smem[];
    float* sBuf = smem;                               // 128 x LDA
    float* sStg = smem + 128 * LDA;                   // 2 x STAGE_FLOATS
    int*   sSeg = (int*)(sStg + 2 * STAGE_FLOATS);    // 128
    int*   sCB  = sSeg + 128;                         // 128
    float* sB1  = (float*)(sCB + 128);                // 256
    float* sB2  = sB1 + 256;                          // 256
    float* sB3  = sB2 + 256;                          // 16

    const int tid  = threadIdx.x;
    const int lane = tid & 31;
    const int wid  = tid >> 5;
    const int g    = lane >> 2;
    const int tig  = lane & 3;
    const int base = blockIdx.x * TILE_M;

    // kick off W1 chunk 0 immediately (overlaps with input staging)
    prefetch_chunk(sStg, gW1, 0);
    cp_commit();

    // ---- indices + biases ----
    if (tid < 128) {
        int c = base + tid, cb = 0, seg = -1;
        if (c < N_CELLS) { cb = c2b[c]; seg = sidx[cb]; }
        sCB[tid] = cb;
        sSeg[tid] = seg;
    }
    if (tid < 256) { sB1[tid] = b1[tid]; sB2[tid] = b2[tid]; }
    if (tid < 16) sB3[tid] = b3[tid];
    __syncthreads();

    // ---- build Xp tile (tf32-rounded) ----
    for (int idx = tid; idx < 128 * 32; idx += 256) {      // X part: log1p
        int row = idx >> 5, q = idx & 31;
        int c = base + row;
        float4 v = make_float4(0.f, 0.f, 0.f, 0.f);
        if (c < N_CELLS) {
            float4 x = *reinterpret_cast<const float4*>(X + (size_t)c * D_X + q * 4);
            v.x = tf32r(__logf(1.0f + x.x));
            v.y = tf32r(__logf(1.0f + x.y));
            v.z = tf32r(__logf(1.0f + x.z));
            v.w = tf32r(__logf(1.0f + x.w));
        }
        *reinterpret_cast<float4*>(sBuf + row * LDA + q * 4) = v;
    }
    for (int idx = tid; idx < 128 * 8; idx += 256) {       // Z part: gather
        int row = idx >> 3, q = idx & 7;
        int c = base + row;
        float4 v = make_float4(0.f, 0.f, 0.f, 0.f);
        if (c < N_CELLS) {
            float4 z = *reinterpret_cast<const float4*>(Z + (size_t)sCB[row] * D_Z + q * 4);
            v.x = tf32r(z.x); v.y = tf32r(z.y); v.z = tf32r(z.z); v.w = tf32r(z.w);
        }
        *reinterpret_cast<float4*>(sBuf + row * LDA + D_X + q * 4) = v;
    }
    __syncthreads();

    const int mg = wid & 1, ng = wid >> 1;
    const int m0 = mg * 64, n0 = ng * 64;

    float acc[4][8][4];

    // ---- layer 1: Xp(128x160) @ W1(160x256), 5 chunks, stages 0,1,0,1,0 ----
#pragma unroll
    for (int mt = 0; mt < 4; mt++)
#pragma unroll
        for (int nt = 0; nt < 8; nt++)
#pragma unroll
            for (int i = 0; i < 4; i++) acc[mt][nt][i] = 0.0f;

    const int NC1 = D_IN / KC;   // 5
    for (int c = 0; c < NC1; c++) {
        if (c + 1 < NC1) prefetch_chunk(sStg + ((c + 1) & 1) * STAGE_FLOATS, gW1, c + 1);
        else             prefetch_chunk(sStg + ((c + 1) & 1) * STAGE_FLOATS, gW2, 0);
        cp_commit();
        cp_wait<1>();
        __syncthreads();                 // chunk c ready; prior compute done
        compute_chunk(sBuf, sStg + (c & 1) * STAGE_FLOATS, m0, n0, g, tig, c * KC, acc);
        __syncthreads();                 // stage (c&1) free before iter c+2 prefetch
    }
    store_act(sBuf, sB1, m0, n0, g, tig, acc);   // sBuf reads done (sync above)
    __syncthreads();

    // ---- layer 2: h1(128x256) @ W2(256x256), 8 chunks, stages start at 1 ----
#pragma unroll
    for (int mt = 0; mt < 4; mt++)
#pragma unroll
        for (int nt = 0; nt < 8; nt++)
#pragma unroll
            for (int i = 0; i < 4; i++) acc[mt][nt][i] = 0.0f;

    const int NC2 = HID / KC;    // 8
    for (int c = 0; c < NC2; c++) {
        int snext = (1 + c + 1) & 1;
        if (c + 1 < NC2) prefetch_chunk(sStg + snext * STAGE_FLOATS, gW2, c + 1);
        else             prefetch_w3(sStg + snext * STAGE_FLOATS, gW3);
        cp_commit();
        cp_wait<1>();
        __syncthreads();
        compute_chunk(sBuf, sStg + ((1 + c) & 1) * STAGE_FLOATS, m0, n0, g, tig, c * KC, acc);
        __syncthreads();
    }
    store_act(sBuf, sB2, m0, n0, g, tig, acc);
    cp_wait<0>();                        // W3 stage landed (this thread's copies)
    __syncthreads();                     // all threads' copies + h2 visible

    // ---- layer 3: h2(128x256) @ W3(256x16) from smem; warp owns 16 rows ----
    const float* sW3 = sStg + ((1 + NC2) & 1) * STAGE_FLOATS;
    float acc3[2][4];
#pragma unroll
    for (int nt = 0; nt < 2; nt++)
#pragma unroll
        for (int i = 0; i < 4; i++) acc3[nt][i] = 0.0f;

    const int r0w = wid * 16;
#pragma unroll 4
    for (int k0 = 0; k0 < HID; k0 += 8) {
        const float* p  = sBuf + (r0w + g) * LDA + k0 + tig;
        const float* p8 = p + 8 * LDA;
        uint32_t a0 = __float_as_uint(p[0]);
        uint32_t a1 = __float_as_uint(p8[0]);
        uint32_t a2 = __float_as_uint(p[4]);
        uint32_t a3 = __float_as_uint(p8[4]);
#pragma unroll
        for (int nt = 0; nt < 2; nt++) {
            int col = nt * 8 + g;
            uint32_t b0 = __float_as_uint(sW3[(k0 + tig) * LDB3 + col]);
            uint32_t b1 = __float_as_uint(sW3[(k0 + tig + 4) * LDB3 + col]);
            mma8(acc3[nt], a0, a1, a2, a3, b0, b1);
        }
    }

    // ---- epilogue: bias + segment reduction (RED atomics) ----
    const int rA = r0w + g, rB = rA + 8;
    const int segA = sSeg[rA], segB = sSeg[rB];
#pragma unroll
    for (int nt = 0; nt < 2; nt++) {
        int c0 = nt * 8 + 2 * tig;
        float bv0 = sB3[c0], bv1 = sB3[c0 + 1];
        if (segA >= 0) {
            atomicAdd(&gSum[segA * D_OUT + c0],     acc3[nt][0] + bv0);
            atomicAdd(&gSum[segA * D_OUT + c0 + 1], acc3[nt][1] + bv1);
        }
        if (segB >= 0) {
            atomicAdd(&gSum[segB * D_OUT + c0],     acc3[nt][2] + bv0);
            atomicAdd(&gSum[segB * D_OUT + c0 + 1], acc3[nt][3] + bv1);
        }
    }
    if (tig == 0) {
        if (segA >= 0) atomicAdd(&gCnt[segA], 1.0f);
        if (segB >= 0) atomicAdd(&gCnt[segB], 1.0f);
    }
}

// ---------------------------------------------------------------------------
__global__ void finalize_kernel(float* __restrict__ out) {
    int i = blockIdx.x * blockDim.x + threadIdx.x;
    if (i < BATCH * D_OUT)
        out[i] = gSum[i] / fmaxf(gCnt[i >> 4], 1.0f);
}

// ---------------------------------------------------------------------------
extern "C" void kernel_launch(void* const* d_in, const int* in_sizes, int n_in,
                              void* d_out, int out_size) {
    const float* X    = (const float*)d_in[0];
    const float* Z    = (const float*)d_in[1];
    const float* W1   = (const float*)d_in[2];
    const float* b1   = (const float*)d_in[3];
    const float* W2   = (const float*)d_in[4];
    const float* b2   = (const float*)d_in[5];
    const float* W3   = (const float*)d_in[6];
    const float* b3   = (const float*)d_in[7];
    const int*   c2b  = (const int*)d_in[8];    // int32 on the wire (JAX x64 off)
    const int*   sidx = (const int*)d_in[9];    // int32 on the wire
    float* out = (float*)d_out;

    cudaFuncSetAttribute(fused_kernel, cudaFuncAttributeMaxDynamicSharedMemorySize,
                         SMEM_BYTES);

    prep_kernel<<<160, 256>>>(W1, W2, W3);
    fused_kernel<<<NTILES, 256, SMEM_BYTES>>>(X, Z, b1, b2, b3, c2b, sidx);
    finalize_kernel<<<(BATCH * D_OUT + 255) / 256, 256>>>(out);
}

// round 11
// speedup vs baseline: 3.0972x; 1.3554x over previous
#include <cuda_runtime.h>
#include <cuda_fp16.h>
#include <cstdint>

// ---------------------------------------------------------------------------
// CompositionModel — fp16 mma.sync m16n8k16 + cp.async weight staging.
//   Xp = [fp16(log1p X) | fp16(Z[c2b])]  (N x 160)
//   h1 = relu(Xp@W1+b1); h2 = relu(h1@W2+b2); Xc = h2@W3+b3; Y = segmean(Xc)
// fp16 mantissa == tf32 mantissa (10 bits) -> same error profile as the
// passing tf32 kernel (rel_err 3.09e-4) at HALF the MMA instruction count.
// tcgen05 is unavailable: harness compiles PTX at compute_103 (no 'a').
// ---------------------------------------------------------------------------

#define N_CELLS 500000
#define D_X     128
#define D_Z     32
#define D_IN    160
#define HID     256
#define D_OUT   16
#define BATCH   512
#define TILE_M  128
#define NTILES  ((N_CELLS + TILE_M - 1) / TILE_M)   // 3907

#define LDAW    132      // act row stride in 32-bit words (2 fp16/word); 132%32=4 -> 4g+tig injective
#define LDBW    20       // weight-stage row stride (words/ n-row); 20 -> 20g+tig injective mod 32
#define LDW3    132      // W3 stage row stride (words)
#define KC      32       // fp16 k-values per chunk (2 k-steps of 16)
#define STAGE_WORDS (256 * LDBW)          // 5120 words = 20 KB

// smem byte offsets
#define SM_BUF  0                                  // 128 x LDAW words = 67584 B
#define SM_STG0 67584                              // 20480 B
#define SM_STG1 88064                              // 20480 B
#define SM_MISC 108544
#define SMEM_BYTES (SM_MISC + 128*4 + 128*4 + 256*4 + 256*4 + 16*4)   // +3136

// __device__ scratch: weights transposed [N][K] fp16 (K contiguous)
__device__ __half gW1t[256 * D_IN];
__device__ __half gW2t[256 * HID];
__device__ __half gW3t[16 * HID];
__device__ float gSum[BATCH * D_OUT];
__device__ float gCnt[BATCH];

__device__ __forceinline__ void cp16(void* dst_smem, const void* src) {
    uint32_t d = (uint32_t)__cvta_generic_to_shared(dst_smem);
    asm volatile("cp.async.cg.shared.global [%0], [%1], 16;\n" :: "r"(d), "l"(src));
}
#define CP_COMMIT() asm volatile("cp.async.commit_group;\n")
#define CP_WAIT(n)  asm volatile("cp.async.wait_group %0;\n" :: "n"(n))

__device__ __forceinline__ void mma16(float c[4],
                                      uint32_t a0, uint32_t a1, uint32_t a2, uint32_t a3,
                                      uint32_t b0, uint32_t b1) {
    asm volatile(
        "mma.sync.aligned.m16n8k16.row.col.f32.f16.f16.f32 "
        "{%0,%1,%2,%3}, {%4,%5,%6,%7}, {%8,%9}, {%0,%1,%2,%3};\n"
        : "+f"(c[0]), "+f"(c[1]), "+f"(c[2]), "+f"(c[3])
        : "r"(a0), "r"(a1), "r"(a2), "r"(a3), "r"(b0), "r"(b1));
}

__device__ __forceinline__ uint32_t h2bits(__half2 h) {
    return *reinterpret_cast<uint32_t*>(&h);
}

// prefetch one KC-k-slice of a [256][pitch] fp16 weight matrix into a stage
__device__ __forceinline__ void prefetch_chunk(char* stg, const __half* Wt,
                                               int pitch, int chunk) {
    int t = threadIdx.x;
#pragma unroll
    for (int u = 0; u < 4; u++) {
        int idx = t + u * 256;            // 0..1023
        int n = idx >> 2, j = idx & 3;    // j: 16B piece (8 fp16) within KC
        cp16(stg + (n * LDBW + j * 4) * 4, Wt + (size_t)n * pitch + chunk * KC + j * 8);
    }
}
// prefetch W3 (16 x 256 fp16 = 8 KB) into a stage, row stride LDW3 words
__device__ __forceinline__ void prefetch_w3(char* stg) {
    int t = threadIdx.x;
#pragma unroll
    for (int u = 0; u < 2; u++) {
        int idx = t + u * 256;            // 0..511
        int n = idx >> 5, j = idx & 31;   // 32 pieces of 8 fp16 per row
        cp16(stg + (n * LDW3 + j * 4) * 4, gW3t + n * HID + j * 8);
    }
}

// one KC-slice of the 64x64 warp-tile GEMM (2 k-steps of 16)
__device__ __forceinline__ void compute_chunk(const uint32_t* __restrict__ sBuf,
                                              const uint32_t* __restrict__ sW,
                                              int m0, int n0, int g, int tig, int kbase,
                                              float (&acc)[4][8][4]) {
#pragma unroll
    for (int kk = 0; kk < KC; kk += 16) {
        int kw = (kbase + kk) >> 1;
        uint32_t a[4][4];
#pragma unroll
        for (int mt = 0; mt < 4; mt++) {
            const uint32_t* p = sBuf + (m0 + mt * 16 + g) * LDAW + kw + tig;
            a[mt][0] = p[0];
            a[mt][1] = p[8 * LDAW];
            a[mt][2] = p[4];
            a[mt][3] = p[8 * LDAW + 4];
        }
#pragma unroll
        for (int nt = 0; nt < 8; nt++) {
            int col = n0 + nt * 8 + g;
            const uint32_t* q = sW + col * LDBW + (kk >> 1) + tig;
            uint32_t b0 = q[0], b1 = q[4];
#pragma unroll
            for (int mt = 0; mt < 4; mt++)
                mma16(acc[mt][nt], a[mt][0], a[mt][1], a[mt][2], a[mt][3], b0, b1);
        }
    }
}

// acc -> relu(+bias) -> fp16 pairs into act buffer
__device__ __forceinline__ void store_act(uint32_t* sBuf, const float* bias,
                                          int m0, int n0, int g, int tig,
                                          float (&acc)[4][8][4]) {
#pragma unroll
    for (int mt = 0; mt < 4; mt++) {
        int r0 = m0 + mt * 16 + g;
#pragma unroll
        for (int nt = 0; nt < 8; nt++) {
            int c0 = n0 + nt * 8 + 2 * tig;
            int wc = (n0 >> 1) + nt * 4 + tig;
            float bv0 = bias[c0], bv1 = bias[c0 + 1];
            __half2 lo = __floats2half2_rn(fmaxf(acc[mt][nt][0] + bv0, 0.f),
                                           fmaxf(acc[mt][nt][1] + bv1, 0.f));
            sBuf[r0 * LDAW + wc] = h2bits(lo);
            __half2 hi = __floats2half2_rn(fmaxf(acc[mt][nt][2] + bv0, 0.f),
                                           fmaxf(acc[mt][nt][3] + bv1, 0.f));
            sBuf[(r0 + 8) * LDAW + wc] = h2bits(hi);
        }
    }
}

// ---------------------------------------------------------------------------
__global__ void prep_kernel(const float* __restrict__ W1, const float* __restrict__ W2,
                            const float* __restrict__ W3) {
    int stride = gridDim.x * blockDim.x;
    int t0 = blockIdx.x * blockDim.x + threadIdx.x;
    for (int i = t0; i < 256 * D_IN; i += stride) {
        int n = i / D_IN, k = i - n * D_IN;
        gW1t[i] = __float2half_rn(W1[k * 256 + n]);
    }
    for (int i = t0; i < 256 * HID; i += stride) {
        int n = i >> 8, k = i & 255;
        gW2t[i] = __float2half_rn(W2[k * 256 + n]);
    }
    for (int i = t0; i < 16 * HID; i += stride) {
        int n = i >> 8, k = i & 255;
        gW3t[i] = __float2half_rn(W3[k * 16 + n]);
    }
    for (int i = t0; i < BATCH * D_OUT; i += stride) gSum[i] = 0.f;
    for (int i = t0; i < BATCH; i += stride) gCnt[i] = 0.f;
}

// ---------------------------------------------------------------------------
__global__ __launch_bounds__(256) void fused_kernel(
    const float* __restrict__ X, const float* __restrict__ Z,
    const float* __restrict__ b1, const float* __restrict__ b2,
    const float* __restrict__ b3,
    const int* __restrict__ c2b, const int* __restrict__ sidx) {
    extern __shared__ char smem[];
    uint32_t* sBuf = (uint32_t*)(smem + SM_BUF);     // 128 x LDAW words (fp16 pairs)
    char*     stg0 = smem + SM_STG0;
    char*     stg1 = smem + SM_STG1;
    int*   sSeg = (int*)(smem + SM_MISC);
    int*   sCB  = sSeg + 128;
    float* sB1  = (float*)(sCB + 128);
    float* sB2  = sB1 + 256;
    float* sB3  = sB2 + 256;

    const int tid  = threadIdx.x;
    const int lane = tid & 31;
    const int wid  = tid >> 5;
    const int g    = lane >> 2;
    const int tig  = lane & 3;
    const int base = blockIdx.x * TILE_M;

    // kick off W1 chunk 0 immediately (overlaps input staging)
    prefetch_chunk(stg0, gW1t, D_IN, 0);
    CP_COMMIT();

    // ---- indices + biases ----
    if (tid < 128) {
        int c = base + tid, cb = 0, seg = -1;
        if (c < N_CELLS) { cb = c2b[c]; seg = sidx[cb]; }
        sCB[tid] = cb;
        sSeg[tid] = seg;
    }
    if (tid < 256) { sB1[tid] = b1[tid]; sB2[tid] = b2[tid]; }
    if (tid < 16) sB3[tid] = b3[tid];
    __syncthreads();

    // ---- build Xp tile (fp16): words 0..63 = log1p(X), 64..79 = Z gather ----
#pragma unroll
    for (int u = 0; u < 16; u++) {               // X: 4096 float4 pieces
        int idx = tid + u * 256;
        int row = idx >> 5, p = idx & 31;
        int cell = base + row;
        uint2 w = make_uint2(0u, 0u);
        if (cell < N_CELLS) {
            float4 x = *reinterpret_cast<const float4*>(X + (size_t)cell * D_X + p * 4);
            w.x = h2bits(__floats2half2_rn(__logf(1.f + x.x), __logf(1.f + x.y)));
            w.y = h2bits(__floats2half2_rn(__logf(1.f + x.z), __logf(1.f + x.w)));
        }
        *reinterpret_cast<uint2*>(sBuf + row * LDAW + 2 * p) = w;
    }
#pragma unroll
    for (int u = 0; u < 4; u++) {                // Z: 1024 float4 pieces
        int idx = tid + u * 256;
        int row = idx >> 3, p = idx & 7;
        int cell = base + row;
        uint2 w = make_uint2(0u, 0u);
        if (cell < N_CELLS) {
            float4 z = *reinterpret_cast<const float4*>(Z + (size_t)sCB[row] * D_Z + p * 4);
            w.x = h2bits(__floats2half2_rn(z.x, z.y));
            w.y = h2bits(__floats2half2_rn(z.z, z.w));
        }
        *reinterpret_cast<uint2*>(sBuf + row * LDAW + 64 + 2 * p) = w;
    }
    __syncthreads();

    const int mg = wid & 1, ng = wid >> 1;
    const int m0 = mg * 64, n0 = ng * 64;

    float acc[4][8][4];

    // ---- layer 1: Xp(128x160) @ W1^T, 5 chunks, stages 0,1,0,1,0 ----
#pragma unroll
    for (int mt = 0; mt < 4; mt++)
#pragma unroll
        for (int nt = 0; nt < 8; nt++)
#pragma unroll
            for (int i = 0; i < 4; i++) acc[mt][nt][i] = 0.0f;

    const int NC1 = D_IN / KC;   // 5
    for (int c = 0; c < NC1; c++) {
        char* nextStg = ((c + 1) & 1) ? stg1 : stg0;
        if (c + 1 < NC1) prefetch_chunk(nextStg, gW1t, D_IN, c + 1);
        else             prefetch_chunk(nextStg, gW2t, HID, 0);
        CP_COMMIT();
        CP_WAIT(1);
        __syncthreads();                 // chunk c landed; prior compute done
        compute_chunk(sBuf, (const uint32_t*)((c & 1) ? stg1 : stg0),
                      m0, n0, g, tig, c * KC, acc);
        __syncthreads();                 // stage free before next-next prefetch
    }
    store_act(sBuf, sB1, m0, n0, g, tig, acc);
    __syncthreads();

    // ---- layer 2: h1(128x256) @ W2^T, 8 chunks, stage parity starts at 1 ----
#pragma unroll
    for (int mt = 0; mt < 4; mt++)
#pragma unroll
        for (int nt = 0; nt < 8; nt++)
#pragma unroll
            for (int i = 0; i < 4; i++) acc[mt][nt][i] = 0.0f;

    const int NC2 = HID / KC;    // 8
    for (int c = 0; c < NC2; c++) {
        char* nextStg = ((c + 2) & 1) ? stg1 : stg0;   // (1+c+1)&1
        if (c + 1 < NC2) prefetch_chunk(nextStg, gW2t, HID, c + 1);
        else             prefetch_w3(nextStg);
        CP_COMMIT();
        CP_WAIT(1);
        __syncthreads();
        compute_chunk(sBuf, (const uint32_t*)(((1 + c) & 1) ? stg1 : stg0),
                      m0, n0, g, tig, c * KC, acc);
        __syncthreads();
    }
    store_act(sBuf, sB2, m0, n0, g, tig, acc);
    CP_WAIT(0);                          // W3 stage landed (stage 1)
    __syncthreads();

    // ---- layer 3: h2(128x256) @ W3^T(16x256); each warp owns 16 rows ----
    const uint32_t* sW3 = (const uint32_t*)stg1;
    float acc3[2][4];
#pragma unroll
    for (int nt = 0; nt < 2; nt++)
#pragma unroll
        for (int i = 0; i < 4; i++) acc3[nt][i] = 0.0f;

    const int r0w = wid * 16;
#pragma unroll
    for (int k0 = 0; k0 < HID; k0 += 16) {
        int kw = k0 >> 1;
        const uint32_t* p = sBuf + (r0w + g) * LDAW + kw + tig;
        uint32_t a0 = p[0];
        uint32_t a1 = p[8 * LDAW];
        uint32_t a2 = p[4];
        uint32_t a3 = p[8 * LDAW + 4];
#pragma unroll
        for (int nt = 0; nt < 2; nt++) {
            int col = nt * 8 + g;
            const uint32_t* q = sW3 + col * LDW3 + kw + tig;
            mma16(acc3[nt], a0, a1, a2, a3, q[0], q[4]);
        }
    }

    // ---- epilogue: bias + segment reduction (RED atomics) ----
    const int rA = r0w + g, rB = rA + 8;
    const int segA = sSeg[rA], segB = sSeg[rB];
#pragma unroll
    for (int nt = 0; nt < 2; nt++) {
        int c0 = nt * 8 + 2 * tig;
        float bv0 = sB3[c0], bv1 = sB3[c0 + 1];
        if (segA >= 0) {
            atomicAdd(&gSum[segA * D_OUT + c0],     acc3[nt][0] + bv0);
            atomicAdd(&gSum[segA * D_OUT + c0 + 1], acc3[nt][1] + bv1);
        }
        if (segB >= 0) {
            atomicAdd(&gSum[segB * D_OUT + c0],     acc3[nt][2] + bv0);
            atomicAdd(&gSum[segB * D_OUT + c0 + 1], acc3[nt][3] + bv1);
        }
    }
    if (tig == 0) {
        if (segA >= 0) atomicAdd(&gCnt[segA], 1.0f);
        if (segB >= 0) atomicAdd(&gCnt[segB], 1.0f);
    }
}

// ---------------------------------------------------------------------------
__global__ void finalize_kernel(float* __restrict__ out) {
    int i = blockIdx.x * blockDim.x + threadIdx.x;
    if (i < BATCH * D_OUT)
        out[i] = gSum[i] / fmaxf(gCnt[i >> 4], 1.0f);
}

// ---------------------------------------------------------------------------
extern "C" void kernel_launch(void* const* d_in, const int* in_sizes, int n_in,
                              void* d_out, int out_size) {
    const float* X    = (const float*)d_in[0];
    const float* Z    = (const float*)d_in[1];
    const float* W1   = (const float*)d_in[2];
    const float* b1   = (const float*)d_in[3];
    const float* W2   = (const float*)d_in[4];
    const float* b2   = (const float*)d_in[5];
    const float* W3   = (const float*)d_in[6];
    const float* b3   = (const float*)d_in[7];
    const int*   c2b  = (const int*)d_in[8];    // int32 on the wire (JAX x64 off)
    const int*   sidx = (const int*)d_in[9];
    float* out = (float*)d_out;

    cudaFuncSetAttribute(fused_kernel, cudaFuncAttributeMaxDynamicSharedMemorySize,
                         SMEM_BYTES);

    prep_kernel<<<160, 256>>>(W1, W2, W3);
    fused_kernel<<<NTILES, 256, SMEM_BYTES>>>(X, Z, b1, b2, b3, c2b, sidx);
    finalize_kernel<<<(BATCH * D_OUT + 255) / 256, 256>>>(out);
}

// round 12
// speedup vs baseline: 4.2115x; 1.3598x over previous
#include <cuda_runtime.h>
#include <cuda_fp16.h>
#include <cstdint>

// ---------------------------------------------------------------------------
// CompositionModel — fp16 mma.sync m16n8k16, cp.async staging, 2 CTAs/SM.
//   Xp = [fp16(log1p X) | fp16(Z[c2b])]  (N x 160)
//   h1 = relu(Xp@W1+b1); h2 = relu(h1@W2+b2); Xc = h2@W3+b3; Y = segmean(Xc)
// R11 ran 1 CTA/SM (128 acc regs): all 8 warps crossed staging/store/sync
// phases in lockstep -> ~17K cyc/CTA exposed. This round: TILE_M=64, warp
// tile 32x64 (acc=64 regs), launch_bounds(256,2) -> 2 CTAs/SM fill bubbles.
// ---------------------------------------------------------------------------

#define N_CELLS 500000
#define D_X     128
#define D_Z     32
#define D_IN    160
#define HID     256
#define D_OUT   16
#define BATCH   512
#define TILE_M  64
#define NTILES  ((N_CELLS + TILE_M - 1) / TILE_M)   // 7813

#define LDAW    132      // act row stride in words (2 fp16/word); 4g+tig injective mod 32
#define LDBW    20       // weight-stage row stride (words); 20g+tig injective mod 32
#define LDW3    132      // W3 stage row stride (words)
#define KC      32       // fp16 k per chunk (2 k-steps of 16)

// smem byte offsets
#define SM_BUF  0                                  // 64 x LDAW words = 33792 B
#define SM_STG0 33792                              // 20480 B
#define SM_STG1 54272                              // 20480 B
#define SM_MISC 74752
// misc: seg[64] cb[64] b1[256] b2[256] b3[16]
#define SMEM_BYTES (SM_MISC + 64*4 + 64*4 + 256*4 + 256*4 + 16*4)   // 77376

// __device__ scratch: weights transposed [N][K] fp16 (K contiguous)
__device__ __half gW1t[256 * D_IN];
__device__ __half gW2t[256 * HID];
__device__ __half gW3t[16 * HID];
__device__ float gSum[BATCH * D_OUT];
__device__ float gCnt[BATCH];

__device__ __forceinline__ void cp16(void* dst_smem, const void* src) {
    uint32_t d = (uint32_t)__cvta_generic_to_shared(dst_smem);
    asm volatile("cp.async.cg.shared.global [%0], [%1], 16;\n" :: "r"(d), "l"(src));
}
#define CP_COMMIT() asm volatile("cp.async.commit_group;\n")
#define CP_WAIT(n)  asm volatile("cp.async.wait_group %0;\n" :: "n"(n))

__device__ __forceinline__ void mma16(float c[4],
                                      uint32_t a0, uint32_t a1, uint32_t a2, uint32_t a3,
                                      uint32_t b0, uint32_t b1) {
    asm volatile(
        "mma.sync.aligned.m16n8k16.row.col.f32.f16.f16.f32 "
        "{%0,%1,%2,%3}, {%4,%5,%6,%7}, {%8,%9}, {%0,%1,%2,%3};\n"
        : "+f"(c[0]), "+f"(c[1]), "+f"(c[2]), "+f"(c[3])
        : "r"(a0), "r"(a1), "r"(a2), "r"(a3), "r"(b0), "r"(b1));
}

__device__ __forceinline__ uint32_t h2bits(__half2 h) {
    return *reinterpret_cast<uint32_t*>(&h);
}

// prefetch one KC-k-slice of a [256][pitch] fp16 weight matrix into a stage
__device__ __forceinline__ void prefetch_chunk(char* stg, const __half* Wt,
                                               int pitch, int chunk) {
    int t = threadIdx.x;
#pragma unroll
    for (int u = 0; u < 4; u++) {
        int idx = t + u * 256;            // 0..1023
        int n = idx >> 2, j = idx & 3;    // j: 16B piece (8 fp16) within KC
        cp16(stg + (n * LDBW + j * 4) * 4, Wt + (size_t)n * pitch + chunk * KC + j * 8);
    }
}
// prefetch W3 (16 x 256 fp16 = 8 KB) into a stage, row stride LDW3 words
__device__ __forceinline__ void prefetch_w3(char* stg) {
    int t = threadIdx.x;
#pragma unroll
    for (int u = 0; u < 2; u++) {
        int idx = t + u * 256;            // 0..511
        int n = idx >> 5, j = idx & 31;   // 32 pieces of 8 fp16 per row
        cp16(stg + (n * LDW3 + j * 4) * 4, gW3t + n * HID + j * 8);
    }
}

// one KC-slice of the 32x64 warp-tile GEMM (2 k-steps of 16)
__device__ __forceinline__ void compute_chunk(const uint32_t* __restrict__ sBuf,
                                              const uint32_t* __restrict__ sW,
                                              int m0, int n0, int g, int tig, int kbase,
                                              float (&acc)[2][8][4]) {
#pragma unroll
    for (int kk = 0; kk < KC; kk += 16) {
        int kw = (kbase + kk) >> 1;
        uint32_t a[2][4];
#pragma unroll
        for (int mt = 0; mt < 2; mt++) {
            const uint32_t* p = sBuf + (m0 + mt * 16 + g) * LDAW + kw + tig;
            a[mt][0] = p[0];
            a[mt][1] = p[8 * LDAW];
            a[mt][2] = p[4];
            a[mt][3] = p[8 * LDAW + 4];
        }
#pragma unroll
        for (int nt = 0; nt < 8; nt++) {
            int col = n0 + nt * 8 + g;
            const uint32_t* q = sW + col * LDBW + (kk >> 1) + tig;
            uint32_t b0 = q[0], b1 = q[4];
#pragma unroll
            for (int mt = 0; mt < 2; mt++)
                mma16(acc[mt][nt], a[mt][0], a[mt][1], a[mt][2], a[mt][3], b0, b1);
        }
    }
}

// acc -> relu(+bias) -> fp16 pairs into act buffer
__device__ __forceinline__ void store_act(uint32_t* sBuf, const float* bias,
                                          int m0, int n0, int g, int tig,
                                          float (&acc)[2][8][4]) {
#pragma unroll
    for (int mt = 0; mt < 2; mt++) {
        int r0 = m0 + mt * 16 + g;
#pragma unroll
        for (int nt = 0; nt < 8; nt++) {
            int c0 = n0 + nt * 8 + 2 * tig;
            int wc = (n0 >> 1) + nt * 4 + tig;
            float bv0 = bias[c0], bv1 = bias[c0 + 1];
            __half2 lo = __floats2half2_rn(fmaxf(acc[mt][nt][0] + bv0, 0.f),
                                           fmaxf(acc[mt][nt][1] + bv1, 0.f));
            sBuf[r0 * LDAW + wc] = h2bits(lo);
            __half2 hi = __floats2half2_rn(fmaxf(acc[mt][nt][2] + bv0, 0.f),
                                           fmaxf(acc[mt][nt][3] + bv1, 0.f));
            sBuf[(r0 + 8) * LDAW + wc] = h2bits(hi);
        }
    }
}

// ---------------------------------------------------------------------------
__global__ void prep_kernel(const float* __restrict__ W1, const float* __restrict__ W2,
                            const float* __restrict__ W3) {
    int stride = gridDim.x * blockDim.x;
    int t0 = blockIdx.x * blockDim.x + threadIdx.x;
    for (int i = t0; i < 256 * D_IN; i += stride) {
        int n = i / D_IN, k = i - n * D_IN;
        gW1t[i] = __float2half_rn(W1[k * 256 + n]);
    }
    for (int i = t0; i < 256 * HID; i += stride) {
        int n = i >> 8, k = i & 255;
        gW2t[i] = __float2half_rn(W2[k * 256 + n]);
    }
    for (int i = t0; i < 16 * HID; i += stride) {
        int n = i >> 8, k = i & 255;
        gW3t[i] = __float2half_rn(W3[k * 16 + n]);
    }
    for (int i = t0; i < BATCH * D_OUT; i += stride) gSum[i] = 0.f;
    for (int i = t0; i < BATCH; i += stride) gCnt[i] = 0.f;
}

// ---------------------------------------------------------------------------
// 8 warps as 2(Mg of 32 rows) x 4(Ng of 64 cols); 2 CTAs resident per SM.
// ---------------------------------------------------------------------------
__global__ __launch_bounds__(256, 2) void fused_kernel(
    const float* __restrict__ X, const float* __restrict__ Z,
    const float* __restrict__ b1, const float* __restrict__ b2,
    const float* __restrict__ b3,
    const int* __restrict__ c2b, const int* __restrict__ sidx) {
    extern __shared__ char smem[];
    uint32_t* sBuf = (uint32_t*)(smem + SM_BUF);     // 64 x LDAW words (fp16 pairs)
    char*     stg0 = smem + SM_STG0;
    char*     stg1 = smem + SM_STG1;
    int*   sSeg = (int*)(smem + SM_MISC);
    int*   sCB  = sSeg + 64;
    float* sB1  = (float*)(sCB + 64);
    float* sB2  = sB1 + 256;
    float* sB3  = sB2 + 256;

    const int tid  = threadIdx.x;
    const int lane = tid & 31;
    const int wid  = tid >> 5;
    const int g    = lane >> 2;
    const int tig  = lane & 3;
    const int base = blockIdx.x * TILE_M;

    // kick off W1 chunk 0 immediately (overlaps input staging)
    prefetch_chunk(stg0, gW1t, D_IN, 0);
    CP_COMMIT();

    // ---- indices + biases ----
    if (tid < 64) {
        int c = base + tid, cb = 0, seg = -1;
        if (c < N_CELLS) { cb = c2b[c]; seg = sidx[cb]; }
        sCB[tid] = cb;
        sSeg[tid] = seg;
    }
    if (tid < 256) { sB1[tid] = b1[tid]; sB2[tid] = b2[tid]; }
    if (tid < 16) sB3[tid] = b3[tid];
    __syncthreads();

    // ---- build Xp tile (fp16): words 0..63 = log1p(X), 64..79 = Z gather ----
#pragma unroll
    for (int u = 0; u < 8; u++) {                // X: 2048 float4 pieces (64 rows x 32)
        int idx = tid + u * 256;
        int row = idx >> 5, p = idx & 31;
        int cell = base + row;
        uint2 w = make_uint2(0u, 0u);
        if (cell < N_CELLS) {
            float4 x = *reinterpret_cast<const float4*>(X + (size_t)cell * D_X + p * 4);
            w.x = h2bits(__floats2half2_rn(__logf(1.f + x.x), __logf(1.f + x.y)));
            w.y = h2bits(__floats2half2_rn(__logf(1.f + x.z), __logf(1.f + x.w)));
        }
        *reinterpret_cast<uint2*>(sBuf + row * LDAW + 2 * p) = w;
    }
#pragma unroll
    for (int u = 0; u < 2; u++) {                // Z: 512 float4 pieces (64 rows x 8)
        int idx = tid + u * 256;
        int row = idx >> 3, p = idx & 7;
        int cell = base + row;
        uint2 w = make_uint2(0u, 0u);
        if (cell < N_CELLS) {
            float4 z = *reinterpret_cast<const float4*>(Z + (size_t)sCB[row] * D_Z + p * 4);
            w.x = h2bits(__floats2half2_rn(z.x, z.y));
            w.y = h2bits(__floats2half2_rn(z.z, z.w));
        }
        *reinterpret_cast<uint2*>(sBuf + row * LDAW + 64 + 2 * p) = w;
    }
    __syncthreads();

    const int mg = wid & 1, ng = wid >> 1;
    const int m0 = mg * 32, n0 = ng * 64;

    float acc[2][8][4];

    // ---- layer 1: Xp(64x160) @ W1^T, 5 chunks, stages 0,1,0,1,0 ----
#pragma unroll
    for (int mt = 0; mt < 2; mt++)
#pragma unroll
        for (int nt = 0; nt < 8; nt++)
#pragma unroll
            for (int i = 0; i < 4; i++) acc[mt][nt][i] = 0.0f;

    const int NC1 = D_IN / KC;   // 5
    for (int c = 0; c < NC1; c++) {
        char* nextStg = ((c + 1) & 1) ? stg1 : stg0;
        if (c + 1 < NC1) prefetch_chunk(nextStg, gW1t, D_IN, c + 1);
        else             prefetch_chunk(nextStg, gW2t, HID, 0);
        CP_COMMIT();
        CP_WAIT(1);
        __syncthreads();                 // chunk c landed; prior compute done
        compute_chunk(sBuf, (const uint32_t*)((c & 1) ? stg1 : stg0),
                      m0, n0, g, tig, c * KC, acc);
        __syncthreads();                 // stage free before next-next prefetch
    }
    store_act(sBuf, sB1, m0, n0, g, tig, acc);
    __syncthreads();

    // ---- layer 2: h1(64x256) @ W2^T, 8 chunks, stage parity starts at 1 ----
#pragma unroll
    for (int mt = 0; mt < 2; mt++)
#pragma unroll
        for (int nt = 0; nt < 8; nt++)
#pragma unroll
            for (int i = 0; i < 4; i++) acc[mt][nt][i] = 0.0f;

    const int NC2 = HID / KC;    // 8
    for (int c = 0; c < NC2; c++) {
        char* nextStg = ((c + 2) & 1) ? stg1 : stg0;   // (1+c+1)&1
        if (c + 1 < NC2) prefetch_chunk(nextStg, gW2t, HID, c + 1);
        else             prefetch_w3(nextStg);
        CP_COMMIT();
        CP_WAIT(1);
        __syncthreads();
        compute_chunk(sBuf, (const uint32_t*)(((1 + c) & 1) ? stg1 : stg0),
                      m0, n0, g, tig, c * KC, acc);
        __syncthreads();
    }
    store_act(sBuf, sB2, m0, n0, g, tig, acc);
    CP_WAIT(0);                          // W3 stage landed (stage 1)
    __syncthreads();

    // ---- layer 3: h2(64x256) @ W3^T(16x256); warps 0..3 own 16 rows each ----
    if (wid < 4) {
        const uint32_t* sW3 = (const uint32_t*)stg1;
        float acc3[2][4];
#pragma unroll
        for (int nt = 0; nt < 2; nt++)
#pragma unroll
            for (int i = 0; i < 4; i++) acc3[nt][i] = 0.0f;

        const int r0w = wid * 16;
#pragma unroll
        for (int k0 = 0; k0 < HID; k0 += 16) {
            int kw = k0 >> 1;
            const uint32_t* p = sBuf + (r0w + g) * LDAW + kw + tig;
            uint32_t a0 = p[0];
            uint32_t a1 = p[8 * LDAW];
            uint32_t a2 = p[4];
            uint32_t a3 = p[8 * LDAW + 4];
#pragma unroll
            for (int nt = 0; nt < 2; nt++) {
                int col = nt * 8 + g;
                const uint32_t* q = sW3 + col * LDW3 + kw + tig;
                mma16(acc3[nt], a0, a1, a2, a3, q[0], q[4]);
            }
        }

        // ---- epilogue: bias + segment reduction (RED atomics) ----
        const int rA = r0w + g, rB = rA + 8;
        const int segA = sSeg[rA], segB = sSeg[rB];
#pragma unroll
        for (int nt = 0; nt < 2; nt++) {
            int c0 = nt * 8 + 2 * tig;
            float bv0 = sB3[c0], bv1 = sB3[c0 + 1];
            if (segA >= 0) {
                atomicAdd(&gSum[segA * D_OUT + c0],     acc3[nt][0] + bv0);
                atomicAdd(&gSum[segA * D_OUT + c0 + 1], acc3[nt][1] + bv1);
            }
            if (segB >= 0) {
                atomicAdd(&gSum[segB * D_OUT + c0],     acc3[nt][2] + bv0);
                atomicAdd(&gSum[segB * D_OUT + c0 + 1], acc3[nt][3] + bv1);
            }
        }
        if (tig == 0) {
            if (segA >= 0) atomicAdd(&gCnt[segA], 1.0f);
            if (segB >= 0) atomicAdd(&gCnt[segB], 1.0f);
        }
    }
}

// ---------------------------------------------------------------------------
__global__ void finalize_kernel(float* __restrict__ out) {
    int i = blockIdx.x * blockDim.x + threadIdx.x;
    if (i < BATCH * D_OUT)
        out[i] = gSum[i] / fmaxf(gCnt[i >> 4], 1.0f);
}

// ---------------------------------------------------------------------------
extern "C" void kernel_launch(void* const* d_in, const int* in_sizes, int n_in,
                              void* d_out, int out_size) {
    const float* X    = (const float*)d_in[0];
    const float* Z    = (const float*)d_in[1];
    const float* W1   = (const float*)d_in[2];
    const float* b1   = (const float*)d_in[3];
    const float* W2   = (const float*)d_in[4];
    const float* b2   = (const float*)d_in[5];
    const float* W3   = (const float*)d_in[6];
    const float* b3   = (const float*)d_in[7];
    const int*   c2b  = (const int*)d_in[8];    // int32 on the wire (JAX x64 off)
    const int*   sidx = (const int*)d_in[9];
    float* out = (float*)d_out;

    cudaFuncSetAttribute(fused_kernel, cudaFuncAttributeMaxDynamicSharedMemorySize,
                         SMEM_BYTES);

    prep_kernel<<<160, 256>>>(W1, W2, W3);
    fused_kernel<<<NTILES, 256, SMEM_BYTES>>>(X, Z, b1, b2, b3, c2b, sidx);
    finalize_kernel<<<(BATCH * D_OUT + 255) / 256, 256>>>(out);
}